// round 13
// baseline (speedup 1.0000x reference)
#include <cuda_runtime.h>
#include <cuda_bf16.h>
#include <cstdint>

using bf16  = __nv_bfloat16;
using bf162 = __nv_bfloat162;

// Problem dims: B=8, L=2048, V=1024, D=1024, fp32.
// Both GEMMs: M=2048, N=1024, K=1024 per batch, NT form (both operands K-major).
#define BATCH 8
#define MDIM  2048
#define NDIM  1024
#define KDIM  1024

// ---------------------------------------------------------------------------
// Device scratch (allocation-free rule: __device__ globals)
// ---------------------------------------------------------------------------
__device__ float g_scores[(size_t)BATCH * MDIM * NDIM];   // 64 MB
__device__ bf16  g_Hh [(size_t)BATCH * MDIM * KDIM];      // 32 MB each
__device__ bf16  g_Hl [(size_t)BATCH * MDIM * KDIM];
__device__ bf16  g_Ph [(size_t)BATCH * MDIM * KDIM];
__device__ bf16  g_Pl [(size_t)BATCH * MDIM * KDIM];
__device__ bf16  g_Vbh[(size_t)BATCH * NDIM * KDIM];      // 16 MB each
__device__ bf16  g_Vbl[(size_t)BATCH * NDIM * KDIM];
__device__ bf16  g_VTh[(size_t)BATCH * NDIM * KDIM];      // V transposed
__device__ bf16  g_VTl[(size_t)BATCH * NDIM * KDIM];

// ---------------------------------------------------------------------------
// PTX helpers (baseline sm_80+ features: cp.async, ldmatrix, mma.sync)
// ---------------------------------------------------------------------------
__device__ __forceinline__ uint32_t smem_u32(const void* p) {
    uint32_t a;
    asm("{ .reg .u64 t; cvta.to.shared.u64 t, %1; cvt.u32.u64 %0, t; }" : "=r"(a) : "l"(p));
    return a;
}
#define CP16(dst, src) \
    asm volatile("cp.async.cg.shared.global [%0], [%1], 16;" :: "r"(dst), "l"(src))
#define CP_COMMIT() asm volatile("cp.async.commit_group;" ::: "memory")
#define CP_WAIT1()  asm volatile("cp.async.wait_group 1;"  ::: "memory")

#define LDSM4(R, addr) \
    asm volatile("ldmatrix.sync.aligned.m8n8.x4.shared.b16 {%0,%1,%2,%3}, [%4];" \
        : "=r"((R)[0]), "=r"((R)[1]), "=r"((R)[2]), "=r"((R)[3]) : "r"(addr))

__device__ __forceinline__ void mma_bf16(float* c, const uint32_t* a, const uint32_t* b) {
    asm volatile(
        "mma.sync.aligned.m16n8k16.row.col.f32.bf16.bf16.f32 "
        "{%0,%1,%2,%3}, {%4,%5,%6,%7}, {%8,%9}, {%0,%1,%2,%3};"
        : "+f"(c[0]), "+f"(c[1]), "+f"(c[2]), "+f"(c[3])
        : "r"(a[0]), "r"(a[1]), "r"(a[2]), "r"(a[3]), "r"(b[0]), "r"(b[1]));
}

// ---------------------------------------------------------------------------
// Merged split-conversion kernel (R11 winner).
// ---------------------------------------------------------------------------
#define V_BLOCKS 8192
#define H_BLOCKS 2048

__global__ __launch_bounds__(1024)
void convert_all(const float* __restrict__ H, const float* __restrict__ Vx)
{
    const int bid = blockIdx.x;
    if (bid < V_BLOCKS) {
        __shared__ float tile[32][33];
        const int b   = bid >> 10;
        const int rem = bid & 1023;
        const int by  = rem >> 5;
        const int bx  = rem & 31;
        const int tx  = threadIdx.x & 31;
        const int ty  = threadIdx.x >> 5;
        const size_t base = (size_t)b * NDIM * KDIM;

        const int x = bx * 32 + tx;
        const int y = by * 32 + ty;
        float v = Vx[base + (size_t)y * 1024 + x];
        bf16 h = __float2bfloat16(v);
        bf16 l = __float2bfloat16(v - __bfloat162float(h));
        g_Vbh[base + (size_t)y * 1024 + x] = h;
        g_Vbl[base + (size_t)y * 1024 + x] = l;

        tile[ty][tx] = v;
        __syncthreads();

        const int xt = by * 32 + tx;
        const int yt = bx * 32 + ty;
        float tv = tile[tx][ty];
        bf16 th = __float2bfloat16(tv);
        bf16 tl = __float2bfloat16(tv - __bfloat162float(th));
        g_VTh[base + (size_t)yt * 1024 + xt] = th;
        g_VTl[base + (size_t)yt * 1024 + xt] = tl;
    } else {
        const size_t i = (size_t)(bid - V_BLOCKS) * 1024 + threadIdx.x;
        float4 v0 = ((const float4*)H)[2 * i];
        float4 v1 = ((const float4*)H)[2 * i + 1];
        const float f[8] = {v0.x, v0.y, v0.z, v0.w, v1.x, v1.y, v1.z, v1.w};
        uint32_t hw[4], lw[4];
        #pragma unroll
        for (int q = 0; q < 4; q++) {
            bf16 ha = __float2bfloat16(f[2*q]);
            bf16 hb = __float2bfloat16(f[2*q + 1]);
            bf16 la = __float2bfloat16(f[2*q]     - __bfloat162float(ha));
            bf16 lb = __float2bfloat16(f[2*q + 1] - __bfloat162float(hb));
            bf162 hp(ha, hb), lp(la, lb);
            hw[q] = *(uint32_t*)&hp;
            lw[q] = *(uint32_t*)&lp;
        }
        ((uint4*)g_Hh)[i] = make_uint4(hw[0], hw[1], hw[2], hw[3]);
        ((uint4*)g_Hl)[i] = make_uint4(lw[0], lw[1], lw[2], lw[3]);
    }
}

// ---------------------------------------------------------------------------
// Split-bf16 mma.sync GEMM (NT): C[m,n] = sum_k A[m,k]*B[n,k]
// CTA tile 128x128, BK=64, 4 warps (2 in M x 2 in N), warp tile 64x64.
// 3-stage cp.async pipeline; fragment reloads interleaved between MMA passes
// (pass order p1,p0,p2 so every set reloads right after its last use).
// ---------------------------------------------------------------------------
#define TILE_BYTES  16384                    // 128 rows * 128 B
#define STAGE_BYTES (4 * TILE_BYTES)         // 65536
#define NSTAGE      3
#define SMEM_BYTES  (NSTAGE * STAGE_BYTES)   // 196608

// byte offset of 16B atom (row, chunk) inside a tile, XOR swizzled
#define SWZ(row, ch) ((uint32_t)((row) * 128 + (((ch) ^ ((row) & 7)) << 4)))

__global__ void __launch_bounds__(128, 1)
gemm_split(int mode, float* __restrict__ Out)
{
    extern __shared__ char smem[];
    const uint32_t smb = smem_u32(smem);

    const int tid  = threadIdx.x;
    const int wid  = tid >> 5;
    const int lane = tid & 31;
    const int warp_m = wid >> 1;     // 0..1
    const int warp_n = wid & 1;      // 0..1

    const int b  = blockIdx.z;
    const int m0 = blockIdx.y * 128;
    const int n0 = blockIdx.x * 128;

    const bf16 *Ah, *Al, *Bh, *Bl;
    float* C;
    if (mode == 0) { Ah = g_Hh; Al = g_Hl; Bh = g_Vbh; Bl = g_Vbl; C = g_scores; }
    else           { Ah = g_Ph; Al = g_Pl; Bh = g_VTh; Bl = g_VTl; C = Out;      }

    const bf16* Ahp = Ah + (size_t)b * MDIM * KDIM + (size_t)m0 * KDIM;
    const bf16* Alp = Al + (size_t)b * MDIM * KDIM + (size_t)m0 * KDIM;
    const bf16* Bhp = Bh + (size_t)b * NDIM * KDIM + (size_t)n0 * KDIM;
    const bf16* Blp = Bl + (size_t)b * NDIM * KDIM + (size_t)n0 * KDIM;

    // one chunk = 4 CP16 per thread; 8 chunks cover a full stage (128 thr)
    auto issue_chunk = [&](int s, int kt, int i) {
        const int ke = kt * 64;
        const uint32_t sbase = smb + s * STAGE_BYTES;
        const int c   = tid + i * 128;    // 0..1023
        const int row = c >> 3;           // 0..127
        const int ch  = c & 7;            // 16B chunk within 128B row
        const uint32_t dst = sbase + SWZ(row, ch);
        const size_t  goff = (size_t)row * KDIM + ke + ch * 8;
        CP16(dst + 0 * TILE_BYTES, Ahp + goff);
        CP16(dst + 1 * TILE_BYTES, Alp + goff);
        CP16(dst + 2 * TILE_BYTES, Bhp + goff);
        CP16(dst + 3 * TILE_BYTES, Blp + goff);
    };
    auto load_stage = [&](int s, int kt) {
        #pragma unroll
        for (int i = 0; i < 8; i++) issue_chunk(s, kt, i);
    };

    // fragment addressing (constant per thread)
    const int arow = warp_m * 64 + (lane & 15);
    const int asel = (lane >> 4);
    const int brow = warp_n * 64 + (lane & 7) + ((lane >> 4) & 1) * 8;
    const int bsel = ((lane >> 3) & 1);

    // single-buffered fragments: A 4 m-tiles, B 8 n-tiles, hi/lo
    uint32_t aFh[4][4], aFl[4][4];
    uint32_t bFh[8][2], bFl[8][2];

    auto load_aFh = [&](uint32_t sb, int ks) {
        const int kch = ks * 2;
        #pragma unroll
        for (int mi = 0; mi < 4; mi++)
            LDSM4(aFh[mi], sb + 0 * TILE_BYTES + SWZ(arow + mi * 16, kch + asel));
    };
    auto load_aFl = [&](uint32_t sb, int ks) {
        const int kch = ks * 2;
        #pragma unroll
        for (int mi = 0; mi < 4; mi++)
            LDSM4(aFl[mi], sb + 1 * TILE_BYTES + SWZ(arow + mi * 16, kch + asel));
    };
    auto load_bFh = [&](uint32_t sb, int ks) {
        const int kch = ks * 2;
        #pragma unroll
        for (int np = 0; np < 4; np++) {
            uint32_t r4[4];
            LDSM4(r4, sb + 2 * TILE_BYTES + SWZ(brow + np * 16, kch + bsel));
            bFh[np*2][0]   = r4[0]; bFh[np*2][1]   = r4[1];
            bFh[np*2+1][0] = r4[2]; bFh[np*2+1][1] = r4[3];
        }
    };
    auto load_bFl = [&](uint32_t sb, int ks) {
        const int kch = ks * 2;
        #pragma unroll
        for (int np = 0; np < 4; np++) {
            uint32_t r4[4];
            LDSM4(r4, sb + 3 * TILE_BYTES + SWZ(brow + np * 16, kch + bsel));
            bFl[np*2][0]   = r4[0]; bFl[np*2][1]   = r4[1];
            bFl[np*2+1][0] = r4[2]; bFl[np*2+1][1] = r4[3];
        }
    };

    float acc[4][8][4];
    #pragma unroll
    for (int mi = 0; mi < 4; mi++)
        #pragma unroll
        for (int ni = 0; ni < 8; ni++)
            #pragma unroll
            for (int r = 0; r < 4; r++) acc[mi][ni][r] = 0.f;

    load_stage(0, 0); CP_COMMIT();
    load_stage(1, 1); CP_COMMIT();

    const int NKT = KDIM / 64;  // 16
    for (int kt = 0; kt < NKT; kt++) {
        CP_WAIT1();              // stage kt resident (<=1 group pending)
        __syncthreads();         // all warps done reading stage (kt+2)%3

        const uint32_t sb = smb + (kt % NSTAGE) * STAGE_BYTES;
        const bool prefetch = (kt + 2 < NKT);
        const int  ps = (kt + 2) % NSTAGE;

        // prime all fragment sets for block ks=0
        load_aFh(sb, 0); load_bFl(sb, 0); load_bFh(sb, 0); load_aFl(sb, 0);

        #pragma unroll
        for (int ks = 0; ks < 4; ks++) {
            // interleave next-stage global loads
            if (prefetch) { issue_chunk(ps, kt + 2, 2 * ks); issue_chunk(ps, kt + 2, 2 * ks + 1); }

            // p1: Ah * Bl   (last use of bFl)
            #pragma unroll
            for (int mi = 0; mi < 4; mi++)
                #pragma unroll
                for (int ni = 0; ni < 8; ni++)
                    mma_bf16(acc[mi][ni], aFh[mi], bFl[ni]);
            if (ks < 3) load_bFl(sb, ks + 1);

            // p0: Ah * Bh   (last use of aFh)
            #pragma unroll
            for (int mi = 0; mi < 4; mi++)
                #pragma unroll
                for (int ni = 0; ni < 8; ni++)
                    mma_bf16(acc[mi][ni], aFh[mi], bFh[ni]);
            if (ks < 3) load_aFh(sb, ks + 1);

            // p2: Al * Bh   (last use of aFl, bFh)
            #pragma unroll
            for (int mi = 0; mi < 4; mi++)
                #pragma unroll
                for (int ni = 0; ni < 8; ni++)
                    mma_bf16(acc[mi][ni], aFl[mi], bFh[ni]);
            if (ks < 3) { load_aFl(sb, ks + 1); load_bFh(sb, ks + 1); }
        }
        CP_COMMIT();
    }

    // ---- epilogue: fp32 stores ----
    float* Cb = C + (size_t)b * MDIM * NDIM;
    #pragma unroll
    for (int mi = 0; mi < 4; mi++) {
        const int r = m0 + warp_m * 64 + mi * 16 + (lane >> 2);
        #pragma unroll
        for (int ni = 0; ni < 8; ni++) {
            const int cc = n0 + warp_n * 64 + ni * 8 + (lane & 3) * 2;
            *(float2*)&Cb[(size_t)r       * NDIM + cc] = make_float2(acc[mi][ni][0], acc[mi][ni][1]);
            *(float2*)&Cb[(size_t)(r + 8) * NDIM + cc] = make_float2(acc[mi][ni][2], acc[mi][ni][3]);
        }
    }
}

// ---------------------------------------------------------------------------
// Softmax over rows of g_scores (V=1024), output split into P hi/lo.
// ---------------------------------------------------------------------------
__global__ __launch_bounds__(256)
void softmax_split()
{
    const float* p = g_scores + (size_t)blockIdx.x * NDIM;
    const int tid  = threadIdx.x;
    const int lane = tid & 31;
    const int wid  = tid >> 5;

    __shared__ float red_max[8];
    __shared__ float red_sum[8];

    float4 v = ((const float4*)p)[tid];

    float m = fmaxf(fmaxf(v.x, v.y), fmaxf(v.z, v.w));
    #pragma unroll
    for (int o = 16; o > 0; o >>= 1) m = fmaxf(m, __shfl_xor_sync(0xFFFFFFFFu, m, o));
    if (lane == 0) red_max[wid] = m;
    __syncthreads();
    float bmax = red_max[0];
    #pragma unroll
    for (int i = 1; i < 8; i++) bmax = fmaxf(bmax, red_max[i]);

    v.x = __expf(v.x - bmax);
    v.y = __expf(v.y - bmax);
    v.z = __expf(v.z - bmax);
    v.w = __expf(v.w - bmax);

    float s = v.x + v.y + v.z + v.w;
    #pragma unroll
    for (int o = 16; o > 0; o >>= 1) s += __shfl_xor_sync(0xFFFFFFFFu, s, o);
    if (lane == 0) red_sum[wid] = s;
    __syncthreads();
    float tot = 0.f;
    #pragma unroll
    for (int i = 0; i < 8; i++) tot += red_sum[i];
    const float inv = __frcp_rn(tot);

    v.x *= inv; v.y *= inv; v.z *= inv; v.w *= inv;

    bf16 h0 = __float2bfloat16(v.x), h1 = __float2bfloat16(v.y);
    bf16 h2 = __float2bfloat16(v.z), h3 = __float2bfloat16(v.w);
    bf16 l0 = __float2bfloat16(v.x - __bfloat162float(h0));
    bf16 l1 = __float2bfloat16(v.y - __bfloat162float(h1));
    bf16 l2 = __float2bfloat16(v.z - __bfloat162float(h2));
    bf16 l3 = __float2bfloat16(v.w - __bfloat162float(h3));

    bf162 hp0(h0, h1), hp1(h2, h3), lp0(l0, l1), lp1(l2, l3);
    const size_t i4 = (size_t)blockIdx.x * (NDIM / 4) + tid;    // uint2 index
    ((uint2*)g_Ph)[i4] = make_uint2(*(uint32_t*)&hp0, *(uint32_t*)&hp1);
    ((uint2*)g_Pl)[i4] = make_uint2(*(uint32_t*)&lp0, *(uint32_t*)&lp1);
}

// ---------------------------------------------------------------------------
extern "C" void kernel_launch(void* const* d_in, const int* in_sizes, int n_in,
                              void* d_out, int out_size)
{
    const float* H  = (const float*)d_in[0];   // (8, 2048, 1024)
    const float* Vx = (const float*)d_in[1];   // (8, 1024, 1024)
    float*       O  = (float*)d_out;           // (8, 2048, 1024)

    cudaFuncSetAttribute(gemm_split, cudaFuncAttributeMaxDynamicSharedMemorySize, SMEM_BYTES);

    convert_all<<<V_BLOCKS + H_BLOCKS, 1024>>>(H, Vx);

    dim3 g(NDIM / 128, MDIM / 128, BATCH);     // (8, 16, 8)
    gemm_split<<<g, 128, SMEM_BYTES>>>(0, O);  // scores = H @ V^T

    softmax_split<<<BATCH * MDIM, 256>>>();    // P -> hi/lo

    gemm_split<<<g, 128, SMEM_BYTES>>>(1, O);  // out = P @ V (via VT)
}

// round 14
// speedup vs baseline: 1.2198x; 1.2198x over previous
#include <cuda_runtime.h>
#include <cuda_bf16.h>
#include <cstdint>

using bf16  = __nv_bfloat16;
using bf162 = __nv_bfloat162;

// Problem dims: B=8, L=2048, V=1024, D=1024, fp32.
#define BATCH 8
#define MDIM  2048
#define NDIM  1024
#define KDIM  1024

// ---------------------------------------------------------------------------
// Device scratch (allocation-free rule: __device__ globals)
// ---------------------------------------------------------------------------
__device__ float g_scores[(size_t)BATCH * MDIM * NDIM];   // 64 MB
__device__ bf16  g_Hh [(size_t)BATCH * MDIM * KDIM];
__device__ bf16  g_Hl [(size_t)BATCH * MDIM * KDIM];
__device__ bf16  g_Ph [(size_t)BATCH * MDIM * KDIM];
__device__ bf16  g_Pl [(size_t)BATCH * MDIM * KDIM];
__device__ bf16  g_Vbh[(size_t)BATCH * NDIM * KDIM];
__device__ bf16  g_Vbl[(size_t)BATCH * NDIM * KDIM];
__device__ bf16  g_VTh[(size_t)BATCH * NDIM * KDIM];
__device__ bf16  g_VTl[(size_t)BATCH * NDIM * KDIM];

// ---------------------------------------------------------------------------
// PTX helpers
// ---------------------------------------------------------------------------
__device__ __forceinline__ uint32_t smem_u32(const void* p) {
    uint32_t a;
    asm("{ .reg .u64 t; cvta.to.shared.u64 t, %1; cvt.u32.u64 %0, t; }" : "=r"(a) : "l"(p));
    return a;
}
#define CP16(dst, src) \
    asm volatile("cp.async.cg.shared.global [%0], [%1], 16;" :: "r"(dst), "l"(src))
#define CP_COMMIT() asm volatile("cp.async.commit_group;" ::: "memory")
#define CP_WAIT1()  asm volatile("cp.async.wait_group 1;"  ::: "memory")

#define LDSM4(R, addr) \
    asm volatile("ldmatrix.sync.aligned.m8n8.x4.shared.b16 {%0,%1,%2,%3}, [%4];" \
        : "=r"((R)[0]), "=r"((R)[1]), "=r"((R)[2]), "=r"((R)[3]) : "r"(addr))

__device__ __forceinline__ void mma_bf16(float* c, const uint32_t* a, const uint32_t* b) {
    asm volatile(
        "mma.sync.aligned.m16n8k16.row.col.f32.bf16.bf16.f32 "
        "{%0,%1,%2,%3}, {%4,%5,%6,%7}, {%8,%9}, {%0,%1,%2,%3};"
        : "+f"(c[0]), "+f"(c[1]), "+f"(c[2]), "+f"(c[3])
        : "r"(a[0]), "r"(a[1]), "r"(a[2]), "r"(a[3]), "r"(b[0]), "r"(b[1]));
}

// split one float pair into packed hi (bf16x2) and lo (bf16x2) words
__device__ __forceinline__ void split2(float x, float y, uint32_t& hw, uint32_t& lw) {
    bf162 hp = __float22bfloat162_rn(make_float2(x, y));
    float2 hf = __bfloat1622float2(hp);
    bf162 lp = __float22bfloat162_rn(make_float2(x - hf.x, y - hf.y));
    hw = *(uint32_t*)&hp;
    lw = *(uint32_t*)&lp;
}

// ---------------------------------------------------------------------------
// Merged split-conversion kernel, 256 threads/block.
// Blocks [0, V_BLOCKS): V path — 32x32 fp32 tile, 4 elems/thread (float4),
//   emits Vbh/Vbl (straight) and VTh/VTl (transposed), 8B packed stores.
// Blocks [V_BLOCKS, +H_BLOCKS): H path — 8 floats/thread, 16B stores.
// ---------------------------------------------------------------------------
#define V_BLOCKS 8192                          // 8 b * 32 * 32 tiles
#define H_BLOCKS 8192                          // 16.78M floats / (256 thr * 8)

__global__ __launch_bounds__(256)
void convert_all(const float* __restrict__ H, const float* __restrict__ Vx)
{
    const int bid = blockIdx.x;
    const int t   = threadIdx.x;
    if (bid < V_BLOCKS) {
        __shared__ float tile[32][33];
        const int b   = bid >> 10;
        const int rem = bid & 1023;
        const int by  = rem >> 5;
        const int bx  = rem & 31;
        const int tx  = t & 7;                 // float4 column group
        const int ty  = t >> 3;                // row 0..31
        const size_t base = (size_t)b * NDIM * KDIM;

        const int y = by * 32 + ty;
        const int x = bx * 32 + tx * 4;
        float4 v = *(const float4*)&Vx[base + (size_t)y * 1024 + x];

        uint32_t h0, l0, h1, l1;
        split2(v.x, v.y, h0, l0);
        split2(v.z, v.w, h1, l1);
        const size_t so = (base + (size_t)y * 1024 + x) >> 2;   // uint2 index
        ((uint2*)g_Vbh)[so] = make_uint2(h0, h1);
        ((uint2*)g_Vbl)[so] = make_uint2(l0, l1);

        tile[ty][tx * 4 + 0] = v.x;
        tile[ty][tx * 4 + 1] = v.y;
        tile[ty][tx * 4 + 2] = v.z;
        tile[ty][tx * 4 + 3] = v.w;
        __syncthreads();

        // transposed: thread owns VT row (bx*32 + dl), cols (by*32 + vg*4..+3)
        const int vg = t & 7;
        const int dl = t >> 3;
        float t0 = tile[vg * 4 + 0][dl];
        float t1 = tile[vg * 4 + 1][dl];
        float t2 = tile[vg * 4 + 2][dl];
        float t3 = tile[vg * 4 + 3][dl];
        uint32_t th0, tl0, th1, tl1;
        split2(t0, t1, th0, tl0);
        split2(t2, t3, th1, tl1);
        const size_t to = (base + (size_t)(bx * 32 + dl) * 1024 + by * 32 + vg * 4) >> 2;
        ((uint2*)g_VTh)[to] = make_uint2(th0, th1);
        ((uint2*)g_VTl)[to] = make_uint2(tl0, tl1);
    } else {
        // H path: 8 consecutive floats per thread
        const size_t gi = (size_t)(bid - V_BLOCKS) * 256 + t;   // 8-float group
        float4 v0 = ((const float4*)H)[2 * gi];
        float4 v1 = ((const float4*)H)[2 * gi + 1];
        uint32_t hw[4], lw[4];
        split2(v0.x, v0.y, hw[0], lw[0]);
        split2(v0.z, v0.w, hw[1], lw[1]);
        split2(v1.x, v1.y, hw[2], lw[2]);
        split2(v1.z, v1.w, hw[3], lw[3]);
        ((uint4*)g_Hh)[gi] = make_uint4(hw[0], hw[1], hw[2], hw[3]);
        ((uint4*)g_Hl)[gi] = make_uint4(lw[0], lw[1], lw[2], lw[3]);
    }
}

// ---------------------------------------------------------------------------
// Split-bf16 mma.sync GEMM (NT) — identical to R12 (best measured config).
// CTA tile 128x128, BK=64, 8 warps (2Mx4N), warp tile 64x32, 3-stage cp.async,
// cp.async interleaved into compute, ldmatrix fragments double-buffered.
// ---------------------------------------------------------------------------
#define TILE_BYTES  16384
#define STAGE_BYTES (4 * TILE_BYTES)
#define NSTAGE      3
#define SMEM_BYTES  (NSTAGE * STAGE_BYTES)

#define SWZ(row, ch) ((uint32_t)((row) * 128 + (((ch) ^ ((row) & 7)) << 4)))

__global__ void __launch_bounds__(256, 1)
gemm_split(int mode, float* __restrict__ Out)
{
    extern __shared__ char smem[];
    const uint32_t smb = smem_u32(smem);

    const int tid  = threadIdx.x;
    const int wid  = tid >> 5;
    const int lane = tid & 31;
    const int warp_m = wid >> 2;
    const int warp_n = wid & 3;

    const int b  = blockIdx.z;
    const int m0 = blockIdx.y * 128;
    const int n0 = blockIdx.x * 128;

    const bf16 *Ah, *Al, *Bh, *Bl;
    float* C;
    if (mode == 0) { Ah = g_Hh; Al = g_Hl; Bh = g_Vbh; Bl = g_Vbl; C = g_scores; }
    else           { Ah = g_Ph; Al = g_Pl; Bh = g_VTh; Bl = g_VTl; C = Out;      }

    const bf16* Ahp = Ah + (size_t)b * MDIM * KDIM + (size_t)m0 * KDIM;
    const bf16* Alp = Al + (size_t)b * MDIM * KDIM + (size_t)m0 * KDIM;
    const bf16* Bhp = Bh + (size_t)b * NDIM * KDIM + (size_t)n0 * KDIM;
    const bf16* Blp = Bl + (size_t)b * NDIM * KDIM + (size_t)n0 * KDIM;

    auto issue_chunk = [&](int s, int kt, int i) {
        const int ke = kt * 64;
        const uint32_t sbase = smb + s * STAGE_BYTES;
        const int c   = tid + i * 256;
        const int row = c >> 3;
        const int ch  = c & 7;
        const uint32_t dst = sbase + SWZ(row, ch);
        const size_t  goff = (size_t)row * KDIM + ke + ch * 8;
        CP16(dst + 0 * TILE_BYTES, Ahp + goff);
        CP16(dst + 1 * TILE_BYTES, Alp + goff);
        CP16(dst + 2 * TILE_BYTES, Bhp + goff);
        CP16(dst + 3 * TILE_BYTES, Blp + goff);
    };
    auto load_stage = [&](int s, int kt) {
        #pragma unroll
        for (int i = 0; i < 4; i++) issue_chunk(s, kt, i);
    };

    const int arow = warp_m * 64 + (lane & 15);
    const int asel = (lane >> 4);
    const int brow = warp_n * 32 + (lane & 7) + ((lane >> 4) & 1) * 8;
    const int bsel = ((lane >> 3) & 1);

    uint32_t aF[2][2][4][4];
    uint32_t bF[2][2][4][2];

    auto load_frags = [&](int buf, uint32_t sb, int ks) {
        const int kch = ks * 2;
        #pragma unroll
        for (int mi = 0; mi < 4; mi++) {
            const uint32_t addr = sb + SWZ(arow + mi * 16, kch + asel);
            LDSM4(aF[buf][0][mi], addr + 0 * TILE_BYTES);
            LDSM4(aF[buf][1][mi], addr + 1 * TILE_BYTES);
        }
        #pragma unroll
        for (int np = 0; np < 2; np++) {
            const uint32_t addr = sb + 2 * TILE_BYTES + SWZ(brow + np * 16, kch + bsel);
            uint32_t r4[4];
            LDSM4(r4, addr);
            bF[buf][0][np*2][0]   = r4[0]; bF[buf][0][np*2][1]   = r4[1];
            bF[buf][0][np*2+1][0] = r4[2]; bF[buf][0][np*2+1][1] = r4[3];
            LDSM4(r4, addr + TILE_BYTES);
            bF[buf][1][np*2][0]   = r4[0]; bF[buf][1][np*2][1]   = r4[1];
            bF[buf][1][np*2+1][0] = r4[2]; bF[buf][1][np*2+1][1] = r4[3];
        }
    };

    float acc[4][4][4];
    #pragma unroll
    for (int mi = 0; mi < 4; mi++)
        #pragma unroll
        for (int ni = 0; ni < 4; ni++)
            #pragma unroll
            for (int r = 0; r < 4; r++) acc[mi][ni][r] = 0.f;

    load_stage(0, 0); CP_COMMIT();
    load_stage(1, 1); CP_COMMIT();

    const int NKT = KDIM / 64;
    for (int kt = 0; kt < NKT; kt++) {
        CP_WAIT1();
        __syncthreads();

        const uint32_t sb = smb + (kt % NSTAGE) * STAGE_BYTES;
        const bool prefetch = (kt + 2 < NKT);
        const int  ps = (kt + 2) % NSTAGE;

        load_frags(0, sb, 0);

        #pragma unroll
        for (int ks = 0; ks < 4; ks++) {
            const int cur = ks & 1;
            if (prefetch) issue_chunk(ps, kt + 2, ks);
            if (ks < 3) load_frags((ks + 1) & 1, sb, ks + 1);
            #pragma unroll
            for (int mi = 0; mi < 4; mi++)
                #pragma unroll
                for (int ni = 0; ni < 4; ni++)
                    mma_bf16(acc[mi][ni], aF[cur][0][mi], bF[cur][0][ni]);
            #pragma unroll
            for (int mi = 0; mi < 4; mi++)
                #pragma unroll
                for (int ni = 0; ni < 4; ni++)
                    mma_bf16(acc[mi][ni], aF[cur][0][mi], bF[cur][1][ni]);
            #pragma unroll
            for (int mi = 0; mi < 4; mi++)
                #pragma unroll
                for (int ni = 0; ni < 4; ni++)
                    mma_bf16(acc[mi][ni], aF[cur][1][mi], bF[cur][0][ni]);
        }
        CP_COMMIT();
    }

    float* Cb = C + (size_t)b * MDIM * NDIM;
    #pragma unroll
    for (int mi = 0; mi < 4; mi++) {
        const int r = m0 + warp_m * 64 + mi * 16 + (lane >> 2);
        #pragma unroll
        for (int ni = 0; ni < 4; ni++) {
            const int cc = n0 + warp_n * 32 + ni * 8 + (lane & 3) * 2;
            *(float2*)&Cb[(size_t)r       * NDIM + cc] = make_float2(acc[mi][ni][0], acc[mi][ni][1]);
            *(float2*)&Cb[(size_t)(r + 8) * NDIM + cc] = make_float2(acc[mi][ni][2], acc[mi][ni][3]);
        }
    }
}

// ---------------------------------------------------------------------------
// Softmax over rows of g_scores (V=1024), output split into P hi/lo.
// ---------------------------------------------------------------------------
__global__ __launch_bounds__(256)
void softmax_split()
{
    const float* p = g_scores + (size_t)blockIdx.x * NDIM;
    const int tid  = threadIdx.x;
    const int lane = tid & 31;
    const int wid  = tid >> 5;

    __shared__ float red_max[8];
    __shared__ float red_sum[8];

    float4 v = ((const float4*)p)[tid];

    float m = fmaxf(fmaxf(v.x, v.y), fmaxf(v.z, v.w));
    #pragma unroll
    for (int o = 16; o > 0; o >>= 1) m = fmaxf(m, __shfl_xor_sync(0xFFFFFFFFu, m, o));
    if (lane == 0) red_max[wid] = m;
    __syncthreads();
    float bmax = red_max[0];
    #pragma unroll
    for (int i = 1; i < 8; i++) bmax = fmaxf(bmax, red_max[i]);

    v.x = __expf(v.x - bmax);
    v.y = __expf(v.y - bmax);
    v.z = __expf(v.z - bmax);
    v.w = __expf(v.w - bmax);

    float s = v.x + v.y + v.z + v.w;
    #pragma unroll
    for (int o = 16; o > 0; o >>= 1) s += __shfl_xor_sync(0xFFFFFFFFu, s, o);
    if (lane == 0) red_sum[wid] = s;
    __syncthreads();
    float tot = 0.f;
    #pragma unroll
    for (int i = 0; i < 8; i++) tot += red_sum[i];
    const float inv = __frcp_rn(tot);

    v.x *= inv; v.y *= inv; v.z *= inv; v.w *= inv;

    uint32_t h0, l0, h1, l1;
    split2(v.x, v.y, h0, l0);
    split2(v.z, v.w, h1, l1);

    const size_t i4 = (size_t)blockIdx.x * (NDIM / 4) + tid;    // uint2 index
    ((uint2*)g_Ph)[i4] = make_uint2(h0, h1);
    ((uint2*)g_Pl)[i4] = make_uint2(l0, l1);
}

// ---------------------------------------------------------------------------
extern "C" void kernel_launch(void* const* d_in, const int* in_sizes, int n_in,
                              void* d_out, int out_size)
{
    const float* H  = (const float*)d_in[0];   // (8, 2048, 1024)
    const float* Vx = (const float*)d_in[1];   // (8, 1024, 1024)
    float*       O  = (float*)d_out;           // (8, 2048, 1024)

    cudaFuncSetAttribute(gemm_split, cudaFuncAttributeMaxDynamicSharedMemorySize, SMEM_BYTES);

    convert_all<<<V_BLOCKS + H_BLOCKS, 256>>>(H, Vx);

    dim3 g(NDIM / 128, MDIM / 128, BATCH);     // (8, 16, 8)
    gemm_split<<<g, 256, SMEM_BYTES>>>(0, O);  // scores = H @ V^T

    softmax_split<<<BATCH * MDIM, 256>>>();    // P -> hi/lo

    gemm_split<<<g, 256, SMEM_BYTES>>>(1, O);  // out = P @ V (via VT)
}

// round 15
// speedup vs baseline: 1.2341x; 1.0117x over previous
#include <cuda_runtime.h>
#include <cuda_bf16.h>
#include <cstdint>

using bf16  = __nv_bfloat16;
using bf162 = __nv_bfloat162;

// Problem dims: B=8, L=2048, V=1024, D=1024, fp32.
#define BATCH 8
#define MDIM  2048
#define NDIM  1024
#define KDIM  1024

// ---------------------------------------------------------------------------
// Device scratch (allocation-free rule: __device__ globals)
// ---------------------------------------------------------------------------
__device__ float g_scores[(size_t)BATCH * MDIM * NDIM];   // 64 MB
__device__ bf16  g_Hh [(size_t)BATCH * MDIM * KDIM];
__device__ bf16  g_Hl [(size_t)BATCH * MDIM * KDIM];
__device__ bf16  g_Ph [(size_t)BATCH * MDIM * KDIM];
__device__ bf16  g_Pl [(size_t)BATCH * MDIM * KDIM];
__device__ bf16  g_Vbh[(size_t)BATCH * NDIM * KDIM];
__device__ bf16  g_Vbl[(size_t)BATCH * NDIM * KDIM];
__device__ bf16  g_VTh[(size_t)BATCH * NDIM * KDIM];
__device__ bf16  g_VTl[(size_t)BATCH * NDIM * KDIM];

// ---------------------------------------------------------------------------
// PTX helpers
// ---------------------------------------------------------------------------
__device__ __forceinline__ uint32_t smem_u32(const void* p) {
    uint32_t a;
    asm("{ .reg .u64 t; cvta.to.shared.u64 t, %1; cvt.u32.u64 %0, t; }" : "=r"(a) : "l"(p));
    return a;
}
#define CP16(dst, src) \
    asm volatile("cp.async.cg.shared.global [%0], [%1], 16;" :: "r"(dst), "l"(src))
#define CP_COMMIT() asm volatile("cp.async.commit_group;" ::: "memory")
#define CP_WAIT1()  asm volatile("cp.async.wait_group 1;"  ::: "memory")

#define LDSM4(R, addr) \
    asm volatile("ldmatrix.sync.aligned.m8n8.x4.shared.b16 {%0,%1,%2,%3}, [%4];" \
        : "=r"((R)[0]), "=r"((R)[1]), "=r"((R)[2]), "=r"((R)[3]) : "r"(addr))

__device__ __forceinline__ void mma_bf16(float* c, const uint32_t* a, const uint32_t* b) {
    asm volatile(
        "mma.sync.aligned.m16n8k16.row.col.f32.bf16.bf16.f32 "
        "{%0,%1,%2,%3}, {%4,%5,%6,%7}, {%8,%9}, {%0,%1,%2,%3};"
        : "+f"(c[0]), "+f"(c[1]), "+f"(c[2]), "+f"(c[3])
        : "r"(a[0]), "r"(a[1]), "r"(a[2]), "r"(a[3]), "r"(b[0]), "r"(b[1]));
}

// split one float pair into packed hi (bf16x2) and lo (bf16x2) words
__device__ __forceinline__ void split2(float x, float y, uint32_t& hw, uint32_t& lw) {
    bf162 hp = __float22bfloat162_rn(make_float2(x, y));
    float2 hf = __bfloat1622float2(hp);
    bf162 lp = __float22bfloat162_rn(make_float2(x - hf.x, y - hf.y));
    hw = *(uint32_t*)&hp;
    lw = *(uint32_t*)&lp;
}

// ---------------------------------------------------------------------------
// Conversion kernel #1 (pre-GEMM1): H hi/lo + V straight hi/lo only.
// ---------------------------------------------------------------------------
#define V_BLOCKS 2048                          // 8b*1024*1024 / (256thr*8/thr) /2... V: 8.39M elems / (256*4) = 8192? see mapping
#define VS_BLOCKS 8192                         // V straight: 8 b * 1024*1024 / (256*4)
#define H_BLOCKS 8192                          // H: 16.78M / (256*8)

__global__ __launch_bounds__(256)
void convert_main(const float* __restrict__ H, const float* __restrict__ Vx)
{
    const int bid = blockIdx.x;
    const int t   = threadIdx.x;
    if (bid < VS_BLOCKS) {
        // V straight: 4 consecutive floats per thread
        const size_t gi = (size_t)bid * 256 + t;              // float4 index
        float4 v = ((const float4*)Vx)[gi];
        uint32_t h0, l0, h1, l1;
        split2(v.x, v.y, h0, l0);
        split2(v.z, v.w, h1, l1);
        ((uint2*)g_Vbh)[gi] = make_uint2(h0, h1);
        ((uint2*)g_Vbl)[gi] = make_uint2(l0, l1);
    } else {
        // H path: 8 consecutive floats per thread
        const size_t gi = (size_t)(bid - VS_BLOCKS) * 256 + t;
        float4 v0 = ((const float4*)H)[2 * gi];
        float4 v1 = ((const float4*)H)[2 * gi + 1];
        uint32_t hw[4], lw[4];
        split2(v0.x, v0.y, hw[0], lw[0]);
        split2(v0.z, v0.w, hw[1], lw[1]);
        split2(v1.x, v1.y, hw[2], lw[2]);
        split2(v1.z, v1.w, hw[3], lw[3]);
        ((uint4*)g_Hh)[gi] = make_uint4(hw[0], hw[1], hw[2], hw[3]);
        ((uint4*)g_Hl)[gi] = make_uint4(lw[0], lw[1], lw[2], lw[3]);
    }
}

// ---------------------------------------------------------------------------
// Split-bf16 mma.sync GEMM (NT). CTA 128x128, BK=64, 8 warps (2Mx4N),
// warp tile 64x32, 3-stage cp.async. Mainloop schedule:
//   prime hi frags only; lo(cur) loads during pass0; hi(next) during pass1;
//   warp-parity ks stagger spreads LDSM bursts across the crossbar.
// ---------------------------------------------------------------------------
#define TILE_BYTES  16384
#define STAGE_BYTES (4 * TILE_BYTES)
#define NSTAGE      3
#define SMEM_BYTES  (NSTAGE * STAGE_BYTES)

#define SWZ(row, ch) ((uint32_t)((row) * 128 + (((ch) ^ ((row) & 7)) << 4)))

__global__ void __launch_bounds__(256, 1)
gemm_split(int mode, float* __restrict__ Out)
{
    extern __shared__ char smem[];
    const uint32_t smb = smem_u32(smem);

    const int tid  = threadIdx.x;
    const int wid  = tid >> 5;
    const int lane = tid & 31;
    const int warp_m = wid >> 2;
    const int warp_n = wid & 3;
    const int kofs   = (wid & 1) << 1;     // ks stagger: 0 or 2

    const int b  = blockIdx.z;
    const int m0 = blockIdx.y * 128;
    const int n0 = blockIdx.x * 128;

    const bf16 *Ah, *Al, *Bh, *Bl;
    float* C;
    if (mode == 0) { Ah = g_Hh; Al = g_Hl; Bh = g_Vbh; Bl = g_Vbl; C = g_scores; }
    else           { Ah = g_Ph; Al = g_Pl; Bh = g_VTh; Bl = g_VTl; C = Out;      }

    const bf16* Ahp = Ah + (size_t)b * MDIM * KDIM + (size_t)m0 * KDIM;
    const bf16* Alp = Al + (size_t)b * MDIM * KDIM + (size_t)m0 * KDIM;
    const bf16* Bhp = Bh + (size_t)b * NDIM * KDIM + (size_t)n0 * KDIM;
    const bf16* Blp = Bl + (size_t)b * NDIM * KDIM + (size_t)n0 * KDIM;

    auto issue_chunk = [&](int s, int kt, int i) {
        const int ke = kt * 64;
        const uint32_t sbase = smb + s * STAGE_BYTES;
        const int c   = tid + i * 256;
        const int row = c >> 3;
        const int ch  = c & 7;
        const uint32_t dst = sbase + SWZ(row, ch);
        const size_t  goff = (size_t)row * KDIM + ke + ch * 8;
        CP16(dst + 0 * TILE_BYTES, Ahp + goff);
        CP16(dst + 1 * TILE_BYTES, Alp + goff);
        CP16(dst + 2 * TILE_BYTES, Bhp + goff);
        CP16(dst + 3 * TILE_BYTES, Blp + goff);
    };
    auto load_stage = [&](int s, int kt) {
        #pragma unroll
        for (int i = 0; i < 4; i++) issue_chunk(s, kt, i);
    };

    const int arow = warp_m * 64 + (lane & 15);
    const int asel = (lane >> 4);
    const int brow = warp_n * 32 + (lane & 7) + ((lane >> 4) & 1) * 8;
    const int bsel = ((lane >> 3) & 1);

    // hi frags double-buffered; lo frags single-buffered (within-ks lifetime)
    uint32_t aFh[2][4][4], bFh[2][4][2];
    uint32_t aFl[4][4],    bFl[4][2];

    auto load_hi = [&](int buf, uint32_t sb, int ks) {
        const int kch = ks * 2;
        #pragma unroll
        for (int mi = 0; mi < 4; mi++)
            LDSM4(aFh[buf][mi], sb + 0 * TILE_BYTES + SWZ(arow + mi * 16, kch + asel));
        #pragma unroll
        for (int np = 0; np < 2; np++) {
            uint32_t r4[4];
            LDSM4(r4, sb + 2 * TILE_BYTES + SWZ(brow + np * 16, kch + bsel));
            bFh[buf][np*2][0]   = r4[0]; bFh[buf][np*2][1]   = r4[1];
            bFh[buf][np*2+1][0] = r4[2]; bFh[buf][np*2+1][1] = r4[3];
        }
    };
    auto load_lo = [&](uint32_t sb, int ks) {
        const int kch = ks * 2;
        #pragma unroll
        for (int mi = 0; mi < 4; mi++)
            LDSM4(aFl[mi], sb + 1 * TILE_BYTES + SWZ(arow + mi * 16, kch + asel));
        #pragma unroll
        for (int np = 0; np < 2; np++) {
            uint32_t r4[4];
            LDSM4(r4, sb + 3 * TILE_BYTES + SWZ(brow + np * 16, kch + bsel));
            bFl[np*2][0]   = r4[0]; bFl[np*2][1]   = r4[1];
            bFl[np*2+1][0] = r4[2]; bFl[np*2+1][1] = r4[3];
        }
    };

    float acc[4][4][4];
    #pragma unroll
    for (int mi = 0; mi < 4; mi++)
        #pragma unroll
        for (int ni = 0; ni < 4; ni++)
            #pragma unroll
            for (int r = 0; r < 4; r++) acc[mi][ni][r] = 0.f;

    load_stage(0, 0); CP_COMMIT();
    load_stage(1, 1); CP_COMMIT();

    const int NKT = KDIM / 64;
    for (int kt = 0; kt < NKT; kt++) {
        CP_WAIT1();
        __syncthreads();

        const uint32_t sb = smb + (kt % NSTAGE) * STAGE_BYTES;
        const bool prefetch = (kt + 2 < NKT);
        const int  ps = (kt + 2) % NSTAGE;

        load_hi(0, sb, kofs);        // prime: hi frags only (6 LDSM)

        #pragma unroll
        for (int kss = 0; kss < 4; kss++) {
            const int ks  = kss ^ kofs;          // warp-staggered order
            const int cur = kss & 1;
            if (prefetch) issue_chunk(ps, kt + 2, kss);

            // pass0: Ah*Bh — while it runs, fetch lo(cur)
            load_lo(sb, ks);
            #pragma unroll
            for (int mi = 0; mi < 4; mi++)
                #pragma unroll
                for (int ni = 0; ni < 4; ni++)
                    mma_bf16(acc[mi][ni], aFh[cur][mi], bFh[cur][ni]);

            // pass1: Ah*Bl — while it runs, fetch hi(next)
            if (kss < 3) load_hi(cur ^ 1, sb, (kss + 1) ^ kofs);
            #pragma unroll
            for (int mi = 0; mi < 4; mi++)
                #pragma unroll
                for (int ni = 0; ni < 4; ni++)
                    mma_bf16(acc[mi][ni], aFh[cur][mi], bFl[ni]);

            // pass2: Al*Bh
            #pragma unroll
            for (int mi = 0; mi < 4; mi++)
                #pragma unroll
                for (int ni = 0; ni < 4; ni++)
                    mma_bf16(acc[mi][ni], aFl[mi], bFh[cur][ni]);
        }
        CP_COMMIT();
    }

    float* Cb = C + (size_t)b * MDIM * NDIM;
    #pragma unroll
    for (int mi = 0; mi < 4; mi++) {
        const int r = m0 + warp_m * 64 + mi * 16 + (lane >> 2);
        #pragma unroll
        for (int ni = 0; ni < 4; ni++) {
            const int cc = n0 + warp_n * 32 + ni * 8 + (lane & 3) * 2;
            *(float2*)&Cb[(size_t)r       * NDIM + cc] = make_float2(acc[mi][ni][0], acc[mi][ni][1]);
            *(float2*)&Cb[(size_t)(r + 8) * NDIM + cc] = make_float2(acc[mi][ni][2], acc[mi][ni][3]);
        }
    }
}

// ---------------------------------------------------------------------------
// Softmax + VT-split kernel.
// Blocks [0, SM_BLOCKS): softmax over one score row, emit Ph/Pl.
// Blocks [SM_BLOCKS, +VT_BLOCKS): V transpose-split, emit VTh/VTl
//   (needed only by GEMM2, so doing it here overlaps it with softmax).
// ---------------------------------------------------------------------------
#define SM_BLOCKS (BATCH * MDIM)               // 16384
#define VT_BLOCKS (BATCH * 1024)               // 8192: 32x32 tiles, 256 thr, 4/thr

__global__ __launch_bounds__(256)
void softmax_vt(const float* __restrict__ Vx)
{
    const int bid = blockIdx.x;
    const int tid = threadIdx.x;

    if (bid < SM_BLOCKS) {
        const float* p = g_scores + (size_t)bid * NDIM;
        const int lane = tid & 31;
        const int wid  = tid >> 5;

        __shared__ float red_max[8];
        __shared__ float red_sum[8];

        float4 v = ((const float4*)p)[tid];

        float m = fmaxf(fmaxf(v.x, v.y), fmaxf(v.z, v.w));
        #pragma unroll
        for (int o = 16; o > 0; o >>= 1) m = fmaxf(m, __shfl_xor_sync(0xFFFFFFFFu, m, o));
        if (lane == 0) red_max[wid] = m;
        __syncthreads();
        float bmax = red_max[0];
        #pragma unroll
        for (int i = 1; i < 8; i++) bmax = fmaxf(bmax, red_max[i]);

        v.x = __expf(v.x - bmax);
        v.y = __expf(v.y - bmax);
        v.z = __expf(v.z - bmax);
        v.w = __expf(v.w - bmax);

        float s = v.x + v.y + v.z + v.w;
        #pragma unroll
        for (int o = 16; o > 0; o >>= 1) s += __shfl_xor_sync(0xFFFFFFFFu, s, o);
        if (lane == 0) red_sum[wid] = s;
        __syncthreads();
        float tot = 0.f;
        #pragma unroll
        for (int i = 0; i < 8; i++) tot += red_sum[i];
        const float inv = __frcp_rn(tot);

        v.x *= inv; v.y *= inv; v.z *= inv; v.w *= inv;

        uint32_t h0, l0, h1, l1;
        split2(v.x, v.y, h0, l0);
        split2(v.z, v.w, h1, l1);

        const size_t i4 = (size_t)bid * (NDIM / 4) + tid;
        ((uint2*)g_Ph)[i4] = make_uint2(h0, h1);
        ((uint2*)g_Pl)[i4] = make_uint2(l0, l1);
    } else {
        // VT path: one 32x32 tile of V, transposed split
        __shared__ float tile[32][33];
        const int vb  = bid - SM_BLOCKS;
        const int b   = vb >> 10;
        const int rem = vb & 1023;
        const int by  = rem >> 5;
        const int bx  = rem & 31;
        const size_t base = (size_t)b * NDIM * KDIM;

        const int tx = tid & 7;                // float4 col group
        const int ty = tid >> 3;               // row 0..31
        const int y = by * 32 + ty;
        const int x = bx * 32 + tx * 4;
        float4 v = *(const float4*)&Vx[base + (size_t)y * 1024 + x];
        tile[ty][tx * 4 + 0] = v.x;
        tile[ty][tx * 4 + 1] = v.y;
        tile[ty][tx * 4 + 2] = v.z;
        tile[ty][tx * 4 + 3] = v.w;
        __syncthreads();

        const int vg = tid & 7;
        const int dl = tid >> 3;
        float t0 = tile[vg * 4 + 0][dl];
        float t1 = tile[vg * 4 + 1][dl];
        float t2 = tile[vg * 4 + 2][dl];
        float t3 = tile[vg * 4 + 3][dl];
        uint32_t th0, tl0, th1, tl1;
        split2(t0, t1, th0, tl0);
        split2(t2, t3, th1, tl1);
        const size_t to = (base + (size_t)(bx * 32 + dl) * 1024 + by * 32 + vg * 4) >> 2;
        ((uint2*)g_VTh)[to] = make_uint2(th0, th1);
        ((uint2*)g_VTl)[to] = make_uint2(tl0, tl1);
    }
}

// ---------------------------------------------------------------------------
extern "C" void kernel_launch(void* const* d_in, const int* in_sizes, int n_in,
                              void* d_out, int out_size)
{
    const float* H  = (const float*)d_in[0];   // (8, 2048, 1024)
    const float* Vx = (const float*)d_in[1];   // (8, 1024, 1024)
    float*       O  = (float*)d_out;           // (8, 2048, 1024)

    cudaFuncSetAttribute(gemm_split, cudaFuncAttributeMaxDynamicSharedMemorySize, SMEM_BYTES);

    convert_main<<<VS_BLOCKS + H_BLOCKS, 256>>>(H, Vx);

    dim3 g(NDIM / 128, MDIM / 128, BATCH);     // (8, 16, 8)
    gemm_split<<<g, 256, SMEM_BYTES>>>(0, O);  // scores = H @ V^T

    softmax_vt<<<SM_BLOCKS + VT_BLOCKS, 256>>>(Vx);  // P hi/lo + VT hi/lo

    gemm_split<<<g, 256, SMEM_BYTES>>>(1, O);  // out = P @ V (via VT)
}